// round 2
// baseline (speedup 1.0000x reference)
#include <cuda_runtime.h>

// VectorNormSelection: per row of 192 floats (64 vectors of 3), compute exact
// squared norms, select top-16 by norm (descending, ties -> lower index),
// gather selected 3-vectors in sorted order.
//
// Round-2 design: thread-per-row (32 rows/warp), rows staged through padded
// smem with coalesced float4 loads. Selection via partial sorting network:
//   - 4 groups of 16 norms, each sorted descending with Batcher odd-even
//     mergesort (63 CEs, all register-resident, fully unrolled indices)
//   - running top-16 merged with each sorted group via bitonic halving
//     (16 max ops) + descending half-cleaner cascade (32 CEs)
//   - final exact-tie cleanup pass restores lower-index-first order
// Norms use __fmul_rn/__fadd_rn (no FMA contraction) to bit-match the
// reference's (x*x + y*y) + z*z.

#define ROW_F     192
#define ROW_F4    48
#define PAD_F     196          // padded floats per row in smem (784B)
#define NVOUT     16
#define RPB       32           // one warp per block, thread-per-row

// compare-exchange: ensure (va,ia) holds the strictly larger value; ties keep order
__device__ __forceinline__ void ceD(float& va, int& ia, float& vb, int& ib) {
    bool sw = vb > va;
    float tv = va; int ti = ia;
    va = sw ? vb : va;  ia = sw ? ib : ia;
    vb = sw ? tv : vb;  ib = sw ? ti : ib;
}

// Batcher odd-even mergesort, n=16, descending (63 comparators, unrolled)
__device__ __forceinline__ void sort16(float (&v)[16], int (&ix)[16]) {
#pragma unroll
    for (int p = 1; p < 16; p <<= 1) {
#pragma unroll
        for (int k = p; k >= 1; k >>= 1) {
#pragma unroll
            for (int j = k & (p - 1); j + k < 16; j += 2 * k) {
#pragma unroll
                for (int i = 0; i < k; i++) {
                    if (i + j + k < 16) {
                        if (((i + j) / (2 * p)) == ((i + j + k) / (2 * p))) {
                            ceD(v[i + j], ix[i + j], v[i + j + k], ix[i + j + k]);
                        }
                    }
                }
            }
        }
    }
}

// rv/ri: running top-16 (desc). cv/ci: new sorted group (desc).
// Result: top-16 of union, descending, in rv/ri.
__device__ __forceinline__ void mergeTop(float (&rv)[16], int (&ri)[16],
                                         const float (&cv)[16], const int (&ci)[16]) {
    // bitonic halving: rv[t] = max(rv[t], cv[15-t]) -> contains top-16, bitonic
#pragma unroll
    for (int t = 0; t < 16; t++) {
        bool sw = cv[15 - t] > rv[t];
        rv[t] = sw ? cv[15 - t] : rv[t];
        ri[t] = sw ? ci[15 - t] : ri[t];
    }
    // descending bitonic sort of a bitonic sequence: half-cleaner cascade
#pragma unroll
    for (int j = 8; j >= 1; j >>= 1) {
#pragma unroll
        for (int t = 0; t < 16; t++) {
            if ((t & j) == 0) {
                ceD(rv[t], ri[t], rv[t | j], ri[t | j]);
            }
        }
    }
}

// exact norms for one group of 16 vectors (48 floats) from a smem row
__device__ __forceinline__ void loadNorms(const float* __restrict__ sr, int g,
                                          float (&v)[16], int (&ix)[16]) {
    const float4* s4 = reinterpret_cast<const float4*>(sr + g * 48);
#pragma unroll
    for (int k = 0; k < 4; k++) {
        float4 a = s4[3 * k + 0];
        float4 b = s4[3 * k + 1];
        float4 c = s4[3 * k + 2];
        v[4 * k + 0] = __fadd_rn(__fadd_rn(__fmul_rn(a.x, a.x), __fmul_rn(a.y, a.y)), __fmul_rn(a.z, a.z));
        v[4 * k + 1] = __fadd_rn(__fadd_rn(__fmul_rn(a.w, a.w), __fmul_rn(b.x, b.x)), __fmul_rn(b.y, b.y));
        v[4 * k + 2] = __fadd_rn(__fadd_rn(__fmul_rn(b.z, b.z), __fmul_rn(b.w, b.w)), __fmul_rn(c.x, c.x));
        v[4 * k + 3] = __fadd_rn(__fadd_rn(__fmul_rn(c.y, c.y), __fmul_rn(c.z, c.z)), __fmul_rn(c.w, c.w));
        ix[4 * k + 0] = g * 16 + 4 * k + 0;
        ix[4 * k + 1] = g * 16 + 4 * k + 1;
        ix[4 * k + 2] = g * 16 + 4 * k + 2;
        ix[4 * k + 3] = g * 16 + 4 * k + 3;
    }
}

__global__ void __launch_bounds__(RPB)
vecnorm_topk_kernel(const float* __restrict__ x, float* __restrict__ out, int nrows)
{
    __shared__ float ws[RPB * PAD_F];

    const int lane    = threadIdx.x;          // 0..31
    const int rowBase = blockIdx.x * RPB;
    if (rowBase >= nrows) return;
    const int rowsHere = min(RPB, nrows - rowBase);
    const int total4   = rowsHere * ROW_F4;

    // ---- stage: coalesced global float4 loads -> padded smem rows ----
    const float4* gx = reinterpret_cast<const float4*>(x) + (size_t)rowBase * ROW_F4;
    {
        int r = 0, p = lane;
#pragma unroll 3
        for (int k = 0; k < 48; k++) {
            int g = lane + 32 * k;
            if (g < total4) {
                float4 v = gx[g];
                *reinterpret_cast<float4*>(ws + r * PAD_F + p * 4) = v;
            }
            p += 32;
            if (p >= ROW_F4) { p -= ROW_F4; r += 1; }
        }
    }
    __syncwarp();

    const bool active = (lane < rowsHere);
    const float* sr = ws + lane * PAD_F;      // in-bounds even for inactive lanes

    // ---- partial sort: top-16 of 64 ----
    float rv[16]; int ri[16];
    loadNorms(sr, 0, rv, ri);
    sort16(rv, ri);

#pragma unroll 1
    for (int g = 1; g < 4; g++) {
        float cv[16]; int ci[16];
        loadNorms(sr, g, cv, ci);
        sort16(cv, ci);
        mergeTop(rv, ri, cv, ci);
    }

    // ---- exact-tie cleanup: equal norms must be ordered lower-index-first ----
#pragma unroll
    for (int t = 0; t < 15; t++) {
        bool sw = (rv[t] == rv[t + 1]) && (ri[t] > ri[t + 1]);
        int a = ri[t], b = ri[t + 1];
        ri[t]     = sw ? b : a;
        ri[t + 1] = sw ? a : b;
    }

    // ---- gather selected vectors, write 48 floats as 12 x STG.128 ----
    if (active) {
        float o[48];
#pragma unroll
        for (int j = 0; j < NVOUT; j++) {
            const float* vp = sr + ri[j] * 3;
            o[3 * j + 0] = vp[0];
            o[3 * j + 1] = vp[1];
            o[3 * j + 2] = vp[2];
        }
        float4* op = reinterpret_cast<float4*>(out + (size_t)(rowBase + lane) * 48);
#pragma unroll
        for (int q = 0; q < 12; q++)
            op[q] = make_float4(o[4 * q + 0], o[4 * q + 1], o[4 * q + 2], o[4 * q + 3]);
    }
}

extern "C" void kernel_launch(void* const* d_in, const int* in_sizes, int n_in,
                              void* d_out, int out_size)
{
    const float* x   = (const float*)d_in[0];
    float*       out = (float*)d_out;
    int nrows = in_sizes[0] / ROW_F;
    int grid  = (nrows + RPB - 1) / RPB;
    vecnorm_topk_kernel<<<grid, RPB>>>(x, out, nrows);
}

// round 4
// speedup vs baseline: 2.7807x; 2.7807x over previous
#include <cuda_runtime.h>

// VectorNormSelection, round 4.
// Thread-per-row (32 rows/warp), rows staged through padded smem (coalesced
// float4 loads). Two-pass exact selection:
//  Pass 1 (value-only): 4 groups of 16 norms sorted desc (Batcher, FMNMX),
//    folded via bitonic halving + half-cleaner merges -> exact 16th-largest t.
//  Pass 2: recompute norms, compact all (norm >= t) as (value,index) into an
//    18-slot smem scratch (count>=16 always; ==17 on rare exact boundary ties).
//  Rank: all-pairs exact rank by (value desc, scan-order asc) == top_k tie
//    semantics; scatter indices by rank; gather vectors; 12x STG.128.

#define ROW_F  192
#define ROW_F4 48
#define PAD_F  196          // padded floats per row in smem (784B, odd word stride)
#define RPB    32           // one warp per block, thread-per-row
#define SCR    18           // scratch entries per row

// comparator: a <- max, b <- min (exact on finite floats)
__device__ __forceinline__ void ceMM(float& a, float& b) {
    float lo = fminf(a, b);
    float hi = fmaxf(a, b);
    a = hi; b = lo;
}

// Batcher odd-even mergesort, n=16, descending, value-only (63 comparators)
__device__ __forceinline__ void sort16v(float (&v)[16]) {
#pragma unroll
    for (int p = 1; p < 16; p <<= 1) {
#pragma unroll
        for (int k = p; k >= 1; k >>= 1) {
#pragma unroll
            for (int j = k & (p - 1); j + k < 16; j += 2 * k) {
#pragma unroll
                for (int i = 0; i < k; i++) {
                    if (i + j + k < 16) {
                        if (((i + j) / (2 * p)) == ((i + j + k) / (2 * p)))
                            ceMM(v[i + j], v[i + j + k]);
                    }
                }
            }
        }
    }
}

// exact norms for one quad of vectors (3 float4s = 12 floats = 4 vectors)
__device__ __forceinline__ void quadNorms(float4 a, float4 c, float4 d,
                                          float& n0, float& n1, float& n2, float& n3) {
    n0 = fmaf(a.x, a.x, fmaf(a.y, a.y, a.z * a.z));
    n1 = fmaf(a.w, a.w, fmaf(c.x, c.x, c.y * c.y));
    n2 = fmaf(c.z, c.z, fmaf(c.w, c.w, d.x * d.x));
    n3 = fmaf(d.y, d.y, fmaf(d.z, d.z, d.w * d.w));
}

__device__ __forceinline__ void loadNormsV(const float* __restrict__ sr, int g, float (&v)[16]) {
    const float4* s4 = reinterpret_cast<const float4*>(sr + g * 48);
#pragma unroll
    for (int k = 0; k < 4; k++) {
        float4 a = s4[3 * k + 0];
        float4 c = s4[3 * k + 1];
        float4 d = s4[3 * k + 2];
        quadNorms(a, c, d, v[4 * k + 0], v[4 * k + 1], v[4 * k + 2], v[4 * k + 3]);
    }
}

__global__ void __launch_bounds__(RPB)
vecnorm_topk_kernel(const float* __restrict__ x, float* __restrict__ out, int nrows)
{
    __shared__ float ws[RPB * PAD_F];
    __shared__ unsigned long long sc[RPB * SCR];

    const int lane    = threadIdx.x;          // 0..31
    const int rowBase = blockIdx.x * RPB;
    if (rowBase >= nrows) return;
    const int rowsHere = min(RPB, nrows - rowBase);
    const int total4   = rowsHere * ROW_F4;

    // ---- stage: coalesced global float4 loads -> padded smem rows ----
    const float4* gx = reinterpret_cast<const float4*>(x) + (size_t)rowBase * ROW_F4;
    {
        int r = 0, p = lane;
#pragma unroll 3
        for (int k = 0; k < 48; k++) {
            int g = lane + 32 * k;
            if (g < total4)
                *reinterpret_cast<float4*>(ws + r * PAD_F + p * 4) = gx[g];
            p += 32;
            if (p >= ROW_F4) { p -= ROW_F4; r += 1; }
        }
    }

    // zero this lane's scratch (no cross-lane access -> no sync needed)
    unsigned long long* mysc = sc + lane * SCR;
#pragma unroll
    for (int j = 0; j < SCR; j++) mysc[j] = 0ull;

    __syncwarp();

    const float* sr = ws + lane * PAD_F;      // in-bounds even for inactive lanes

    // ---- pass 1: exact value-only top-16 -> threshold t ----
    float rv[16];
    loadNormsV(sr, 0, rv);
    sort16v(rv);

#pragma unroll 1
    for (int g = 1; g < 3; g++) {
        float cv[16];
        loadNormsV(sr, g, cv);
        sort16v(cv);
        // bitonic halving: rv <- elementwise max(rv[i], cv[15-i])
#pragma unroll
        for (int i = 0; i < 16; i++) rv[i] = fmaxf(rv[i], cv[15 - i]);
        // half-cleaner cascade: restore descending order
#pragma unroll
        for (int j = 8; j >= 1; j >>= 1) {
#pragma unroll
            for (int tt = 0; tt < 16; tt++) {
                if ((tt & j) == 0) ceMM(rv[tt], rv[tt | j]);
            }
        }
    }
    // last group: only need min of halved set (= exact 16th largest)
    float t;
    {
        float cv[16];
        loadNormsV(sr, 3, cv);
        sort16v(cv);
#pragma unroll
        for (int i = 0; i < 16; i++) rv[i] = fmaxf(rv[i], cv[15 - i]);
        float m0 = fminf(fminf(fminf(rv[0],  rv[1]),  fminf(rv[2],  rv[3])),
                         fminf(fminf(rv[4],  rv[5]),  fminf(rv[6],  rv[7])));
        float m1 = fminf(fminf(fminf(rv[8],  rv[9]),  fminf(rv[10], rv[11])),
                         fminf(fminf(rv[12], rv[13]), fminf(rv[14], rv[15])));
        t = fminf(m0, m1);
    }

    // ---- pass 2: compact all (norm >= t) as (value<<32 | index) ----
    int pos = 0;
#pragma unroll 1
    for (int g = 0; g < 4; g++) {
        const float4* s4 = reinterpret_cast<const float4*>(sr + g * 48);
#pragma unroll
        for (int k = 0; k < 4; k++) {
            float4 a = s4[3 * k + 0];
            float4 c = s4[3 * k + 1];
            float4 d = s4[3 * k + 2];
            float n0, n1, n2, n3;
            quadNorms(a, c, d, n0, n1, n2, n3);
            int id0 = g * 16 + 4 * k;
            if (n0 >= t) { mysc[min(pos, SCR - 1)] = ((unsigned long long)__float_as_uint(n0) << 32) | (unsigned)(id0 + 0); pos++; }
            if (n1 >= t) { mysc[min(pos, SCR - 1)] = ((unsigned long long)__float_as_uint(n1) << 32) | (unsigned)(id0 + 1); pos++; }
            if (n2 >= t) { mysc[min(pos, SCR - 1)] = ((unsigned long long)__float_as_uint(n2) << 32) | (unsigned)(id0 + 2); pos++; }
            if (n3 >= t) { mysc[min(pos, SCR - 1)] = ((unsigned long long)__float_as_uint(n3) << 32) | (unsigned)(id0 + 3); pos++; }
        }
    }

    // ---- exact all-pairs rank: (value desc, scan/index asc) ----
    float    v[SCR];
    int      ix[SCR];
    int      rk[SCR];
#pragma unroll
    for (int e = 0; e < SCR; e++) {
        unsigned long long w = mysc[e];
        v[e]  = __uint_as_float((unsigned)(w >> 32));
        ix[e] = (int)(unsigned)(w & 0xffffffffu);
        rk[e] = 0;
    }
#pragma unroll
    for (int e = 0; e < SCR - 1; e++) {
#pragma unroll
        for (int f = e + 1; f < SCR; f++) {
            bool q = v[f] > v[e];     // strict: f beats e
            rk[e] += q;
            rk[f] += !q;              // ties -> earlier scan (lower index) first
        }
    }

    // scatter indices by rank into reused scratch (same-lane region only)
    unsigned* order = reinterpret_cast<unsigned*>(mysc);
#pragma unroll
    for (int e = 0; e < SCR; e++) {
        if (rk[e] < 16) order[rk[e]] = (unsigned)ix[e];
    }

    // ---- gather selected vectors, write 48 floats as 12 x STG.128 ----
    if (lane < rowsHere) {
        float o[48];
#pragma unroll
        for (int j = 0; j < 16; j++) {
            int idx = (int)order[j];
            const float* vp = sr + idx * 3;
            o[3 * j + 0] = vp[0];
            o[3 * j + 1] = vp[1];
            o[3 * j + 2] = vp[2];
        }
        float4* op = reinterpret_cast<float4*>(out + (size_t)(rowBase + lane) * 48);
#pragma unroll
        for (int q = 0; q < 12; q++)
            op[q] = make_float4(o[4 * q + 0], o[4 * q + 1], o[4 * q + 2], o[4 * q + 3]);
    }
}

extern "C" void kernel_launch(void* const* d_in, const int* in_sizes, int n_in,
                              void* d_out, int out_size)
{
    const float* x   = (const float*)d_in[0];
    float*       out = (float*)d_out;
    int nrows = in_sizes[0] / ROW_F;
    int grid  = (nrows + RPB - 1) / RPB;
    vecnorm_topk_kernel<<<grid, RPB>>>(x, out, nrows);
}

// round 5
// speedup vs baseline: 3.2312x; 1.1620x over previous
#include <cuda_runtime.h>

// VectorNormSelection, round 5.
// One warp per block, thread-per-row selection, but NO raw-row smem staging:
//  Phase A: lanes own 4-vector chunks (3 float4 = 48B each). Warp loads two
//    complete rows per iteration (3x LDG.128, every fetched line fully used),
//    computes 4 norms per lane, STS.128 into a norms-only smem array
//    (68-float padded stride, conflict-free).
//  Phase B (per thread = per row): R4's proven exact selection on the 64
//    norms: Batcher sort16 + bitonic-halving merges -> exact 16th-largest t;
//    compaction of (norm >= t) as (val<<32|idx) u64 into an 18-slot scratch;
//    all-pairs stable rank (value desc, scan asc) == jax.lax.top_k semantics;
//    scatter ranked indices.
//  Phase C: warp-cooperative gather straight from global (rows are L2-hot):
//    each row's 48 output floats read by 32 lanes (1.5 loads/lane), stores
//    coalesced.
// smem 13.3KB/block (vs 29.7KB in R4) -> ~17 blocks/SM instead of 7.

#define RPB   32
#define NPAD  68           // norms row stride in floats (272B, conflict-free)
#define SCR   18           // scratch entries per row

// comparator: a <- max, b <- min
__device__ __forceinline__ void ceMM(float& a, float& b) {
    float lo = fminf(a, b);
    float hi = fmaxf(a, b);
    a = hi; b = lo;
}

// Batcher odd-even mergesort, n=16, descending, value-only (63 comparators)
__device__ __forceinline__ void sort16v(float (&v)[16]) {
#pragma unroll
    for (int p = 1; p < 16; p <<= 1) {
#pragma unroll
        for (int k = p; k >= 1; k >>= 1) {
#pragma unroll
            for (int j = k & (p - 1); j + k < 16; j += 2 * k) {
#pragma unroll
                for (int i = 0; i < k; i++) {
                    if (i + j + k < 16) {
                        if (((i + j) / (2 * p)) == ((i + j + k) / (2 * p)))
                            ceMM(v[i + j], v[i + j + k]);
                    }
                }
            }
        }
    }
}

__device__ __forceinline__ void loadN(const float* __restrict__ nr, int g, float (&v)[16]) {
    const float4* p = reinterpret_cast<const float4*>(nr + g * 16);
#pragma unroll
    for (int k = 0; k < 4; k++) {
        float4 q = p[k];
        v[4 * k + 0] = q.x; v[4 * k + 1] = q.y; v[4 * k + 2] = q.z; v[4 * k + 3] = q.w;
    }
}

__global__ void __launch_bounds__(RPB)
vecnorm_topk_kernel(const float* __restrict__ x, float* __restrict__ out, int nrows)
{
    __shared__ float nsm[RPB * NPAD];                 // 8704B: norms, 64/row
    __shared__ unsigned long long sc[RPB * SCR];      // 4608B: scratch

    const int lane    = threadIdx.x;                  // 0..31
    const int rowBase = blockIdx.x * RPB;
    if (rowBase >= nrows) return;
    const int rowsHere = min(RPB, nrows - rowBase);

    unsigned long long* mysc = sc + lane * SCR;
#pragma unroll
    for (int j = 0; j < SCR; j++) mysc[j] = 0ull;

    // ---- Phase A: chunk loads + norms -> smem ----
    const float4* gx = reinterpret_cast<const float4*>(x);
    const int subrow = lane >> 4;                     // 0 or 1
    const int chunk  = lane & 15;                     // 0..15
#pragma unroll 4
    for (int i = 0; i < 16; i++) {
        int lrow = 2 * i + subrow;
        int grow = rowBase + lrow;
        if (grow < nrows) {
            int base = grow * 48 + chunk * 3;         // fits int: < 24M
            float4 a = gx[base + 0];
            float4 b = gx[base + 1];
            float4 d = gx[base + 2];
            float n0 = fmaf(a.x, a.x, fmaf(a.y, a.y, a.z * a.z));
            float n1 = fmaf(a.w, a.w, fmaf(b.x, b.x, b.y * b.y));
            float n2 = fmaf(b.z, b.z, fmaf(b.w, b.w, d.x * d.x));
            float n3 = fmaf(d.y, d.y, fmaf(d.z, d.z, d.w * d.w));
            *reinterpret_cast<float4*>(nsm + lrow * NPAD + chunk * 4) =
                make_float4(n0, n1, n2, n3);
        }
    }
    __syncwarp();

    // ---- Phase B: per-thread exact top-16 selection on own row's norms ----
    if (lane < rowsHere) {
        const float* nr = nsm + lane * NPAD;

        // pass 1: exact threshold t = 16th largest
        float rv[16];
        loadN(nr, 0, rv);
        sort16v(rv);
#pragma unroll 1
        for (int g = 1; g < 3; g++) {
            float cv[16];
            loadN(nr, g, cv);
            sort16v(cv);
#pragma unroll
            for (int i = 0; i < 16; i++) rv[i] = fmaxf(rv[i], cv[15 - i]);
#pragma unroll
            for (int j = 8; j >= 1; j >>= 1) {
#pragma unroll
                for (int tt = 0; tt < 16; tt++)
                    if ((tt & j) == 0) ceMM(rv[tt], rv[tt | j]);
            }
        }
        float t;
        {
            float cv[16];
            loadN(nr, 3, cv);
            sort16v(cv);
#pragma unroll
            for (int i = 0; i < 16; i++) rv[i] = fmaxf(rv[i], cv[15 - i]);
            float m0 = fminf(fminf(fminf(rv[0],  rv[1]),  fminf(rv[2],  rv[3])),
                             fminf(fminf(rv[4],  rv[5]),  fminf(rv[6],  rv[7])));
            float m1 = fminf(fminf(fminf(rv[8],  rv[9]),  fminf(rv[10], rv[11])),
                             fminf(fminf(rv[12], rv[13]), fminf(rv[14], rv[15])));
            t = fminf(m0, m1);
        }

        // pass 2: compact all (norm >= t) in scan order
        int pos = 0;
#pragma unroll 1
        for (int g = 0; g < 4; g++) {
            float cv[16];
            loadN(nr, g, cv);
#pragma unroll
            for (int k = 0; k < 16; k++) {
                if (cv[k] >= t) {
                    mysc[min(pos, SCR - 1)] =
                        ((unsigned long long)__float_as_uint(cv[k]) << 32) |
                        (unsigned)(g * 16 + k);
                    pos++;
                }
            }
        }

        // exact all-pairs stable rank
        float v[SCR]; int ix[SCR]; int rk[SCR];
#pragma unroll
        for (int e = 0; e < SCR; e++) {
            unsigned long long w = mysc[e];
            v[e]  = __uint_as_float((unsigned)(w >> 32));
            ix[e] = (int)(unsigned)(w & 0xffffffffu);
            rk[e] = 0;
        }
#pragma unroll
        for (int e = 0; e < SCR - 1; e++) {
#pragma unroll
            for (int f = e + 1; f < SCR; f++) {
                bool q = v[f] > v[e];
                rk[e] += q;
                rk[f] += !q;
            }
        }
        unsigned* order = reinterpret_cast<unsigned*>(mysc);
#pragma unroll
        for (int e = 0; e < SCR; e++)
            if (rk[e] < 16) order[rk[e]] = (unsigned)ix[e];
    }
    __syncwarp();

    // ---- Phase C: warp-cooperative gather from global (L2-hot rows) ----
    {
        const unsigned* ordBase = reinterpret_cast<const unsigned*>(sc);
        const int j1 = lane / 3,        c1 = lane - 3 * j1;         // out float lane
        const int f2 = 32 + lane;
        const int j2 = f2 / 3,          c2 = f2 - 3 * j2;           // out float 32+lane
#pragma unroll 2
        for (int r = 0; r < rowsHere; r++) {
            int ro = rowBase + r;
            const unsigned* ord = ordBase + r * (2 * SCR);
            unsigned i1 = ord[j1];
            float v1 = x[ro * 192 + (int)i1 * 3 + c1];
            out[ro * 48 + lane] = v1;
            if (lane < 16) {
                unsigned i2 = ord[j2];
                out[ro * 48 + 32 + lane] = x[ro * 192 + (int)i2 * 3 + c2];
            }
        }
    }
}

extern "C" void kernel_launch(void* const* d_in, const int* in_sizes, int n_in,
                              void* d_out, int out_size)
{
    const float* x   = (const float*)d_in[0];
    float*       out = (float*)d_out;
    int nrows = in_sizes[0] / 192;
    int grid  = (nrows + RPB - 1) / RPB;
    vecnorm_topk_kernel<<<grid, RPB>>>(x, out, nrows);
}